// round 1
// baseline (speedup 1.0000x reference)
#include <cuda_runtime.h>
#include <cuda_bf16.h>

// Problem geometry (fixed by the reference):
//   x      : [8192, 4096] fp32, row-major
//   blocks : [4096, 4096] fp32, block-diagonal, 16 blocks of 256x256
//   out    : [8192, 4096] fp32 = x @ tanh(blocks * mask)
// Only the 16 diagonal 256x256 blocks matter; mask is 1 there.

#define NROWS   8192
#define LAYER   4096
#define NBLK    16
#define BSZ     256

// Scratch: tanh'd diagonal blocks, [16][256][256] (4 MB). Allocation-free.
__device__ float g_Bt[NBLK * BSZ * BSZ];

// ---------------------------------------------------------------------------
// Kernel 1: extract diagonal blocks + tanh
// ---------------------------------------------------------------------------
__global__ void prep_blocks_kernel(const float* __restrict__ blocks) {
    int idx = blockIdx.x * blockDim.x + threadIdx.x;   // 0 .. 16*256*256-1
    if (idx >= NBLK * BSZ * BSZ) return;
    int b = idx >> 16;          // block id
    int r = (idx >> 8) & 255;   // row within block
    int c = idx & 255;          // col within block
    float v = blocks[(size_t)(b * BSZ + r) * LAYER + (b * BSZ + c)];
    g_Bt[idx] = tanhf(v);
}

// ---------------------------------------------------------------------------
// Kernel 2: per-block GEMM, classic 128x128x8 register-tiled SGEMM
//   grid.x = M tiles (8192/128 = 64)
//   grid.y = N tiles within a block (256/128 = 2)
//   grid.z = block id (16)
// 256 threads, each computes an 8x8 output tile.
// ---------------------------------------------------------------------------
#define BM 128
#define BN 128
#define BK 8
#define TM 8
#define TN 8

__global__ __launch_bounds__(256, 2)
void blockdiag_gemm_kernel(const float* __restrict__ x,
                           float* __restrict__ out) {
    __shared__ float As[BK][BM];   // transposed A tile
    __shared__ float Bs[BK][BN];

    const int b       = blockIdx.z;
    const int rowTile = blockIdx.x * BM;
    const int nTile   = blockIdx.y * BN;            // 0 or 128 within block
    const int kBase   = b * BSZ;                    // x column offset
    const int colBase = b * BSZ + nTile;            // out column offset

    const float* __restrict__ Bt = g_Bt + (size_t)b * BSZ * BSZ;

    const int tid = threadIdx.x;                    // 0..255
    const int tx  = tid & 15;                       // 0..15 -> N
    const int ty  = tid >> 4;                       // 0..15 -> M

    // global load mapping (float4 each)
    const int aRow = tid >> 1;                      // 0..127
    const int aCol = (tid & 1) * 4;                 // 0 or 4
    const int bRow = tid >> 5;                      // 0..7
    const int bCol = (tid & 31) * 4;                // 0..124

    float acc[TM][TN];
    #pragma unroll
    for (int i = 0; i < TM; i++)
        #pragma unroll
        for (int j = 0; j < TN; j++) acc[i][j] = 0.0f;

    const float* xA = x + (size_t)(rowTile + aRow) * LAYER + kBase + aCol;

    #pragma unroll 1
    for (int k0 = 0; k0 < BSZ; k0 += BK) {
        // load A tile 128x8 -> As (transposed)
        float4 av = *reinterpret_cast<const float4*>(xA + k0);
        As[aCol + 0][aRow] = av.x;
        As[aCol + 1][aRow] = av.y;
        As[aCol + 2][aRow] = av.z;
        As[aCol + 3][aRow] = av.w;
        // load B tile 8x128 -> Bs
        float4 bv = *reinterpret_cast<const float4*>(
            Bt + (size_t)(k0 + bRow) * BSZ + nTile + bCol);
        *reinterpret_cast<float4*>(&Bs[bRow][bCol]) = bv;
        __syncthreads();

        #pragma unroll
        for (int k = 0; k < BK; k++) {
            float4 a0 = *reinterpret_cast<const float4*>(&As[k][ty * TM]);
            float4 a1 = *reinterpret_cast<const float4*>(&As[k][ty * TM + 4]);
            float4 b0 = *reinterpret_cast<const float4*>(&Bs[k][tx * TN]);
            float4 b1 = *reinterpret_cast<const float4*>(&Bs[k][tx * TN + 4]);
            float a[TM] = {a0.x, a0.y, a0.z, a0.w, a1.x, a1.y, a1.z, a1.w};
            float bb[TN] = {b0.x, b0.y, b0.z, b0.w, b1.x, b1.y, b1.z, b1.w};
            #pragma unroll
            for (int i = 0; i < TM; i++)
                #pragma unroll
                for (int j = 0; j < TN; j++)
                    acc[i][j] = fmaf(a[i], bb[j], acc[i][j]);
        }
        __syncthreads();
    }

    // epilogue: 8 rows x 8 cols, two float4 stores per row
    #pragma unroll
    for (int i = 0; i < TM; i++) {
        float* o = out + (size_t)(rowTile + ty * TM + i) * LAYER + colBase + tx * TN;
        *reinterpret_cast<float4*>(o)     = make_float4(acc[i][0], acc[i][1], acc[i][2], acc[i][3]);
        *reinterpret_cast<float4*>(o + 4) = make_float4(acc[i][4], acc[i][5], acc[i][6], acc[i][7]);
    }
}

// ---------------------------------------------------------------------------
extern "C" void kernel_launch(void* const* d_in, const int* in_sizes, int n_in,
                              void* d_out, int out_size) {
    const float* x      = (const float*)d_in[0];
    const float* blocks = (const float*)d_in[1];
    // d_in[2] = mask: unused (diagonal blocks are fully unmasked)
    float* out = (float*)d_out;

    // 1) tanh'd diagonal block extraction: 1M elements
    prep_blocks_kernel<<<(NBLK * BSZ * BSZ) / 256, 256>>>(blocks);

    // 2) block-diagonal GEMM
    dim3 grid(NROWS / BM, BSZ / BN, NBLK);
    blockdiag_gemm_kernel<<<grid, 256>>>(x, out);
}

// round 5
// speedup vs baseline: 1.6372x; 1.6372x over previous
#include <cuda_runtime.h>
#include <cuda_bf16.h>
#include <cstdint>

// out[8192,4096] = x[8192,4096] @ tanh(block_diag), 16 blocks of 256x256.
// bf16-split (hi/lo) warp-level mma.sync (m16n8k16) — arch-portable PTX.
// C = Ah*Bh + Ah*Bl + Al*Bh   (Al*Bl dropped, ~1e-5 rel err)

#define NROWS   8192
#define LAYER   4096
#define NBLK    16
#define BSZ     256

// ---------------------------------------------------------------------------
// Precomputed B images: tanh'd, bf16-split, pre-swizzled for ldmatrix.
// Image = one (block, half, kchunk): [n=128][k=128] bf16, 256B rows,
// 16B-granule XOR swizzle: off = n*256 + (((k>>3) ^ (n&7))<<4) + (k&7)*2.
// 16 blk * 2 half * 2 chunk = 64 images * 32KB = 2MB per array.
__device__ __align__(16) unsigned char g_Bhi[NBLK * 2 * 2 * 32768];
__device__ __align__(16) unsigned char g_Blo[NBLK * 2 * 2 * 32768];

__global__ void prep_b_kernel(const float* __restrict__ blocks) {
    unsigned g = blockIdx.x * blockDim.x + threadIdx.x;   // 1M threads
    int n = g & 127;            // out-col within half
    int k = (g >> 7) & 255;     // K within block
    int h = (g >> 15) & 1;      // N half
    int b = g >> 16;            // block
    float v = tanhf(blocks[(size_t)(b * BSZ + k) * LAYER + b * BSZ + h * 128 + n]);
    __nv_bfloat16 hi = __float2bfloat16(v);
    __nv_bfloat16 lo = __float2bfloat16(v - __bfloat162float(hi));
    int chunk = k >> 7, kk = k & 127;
    size_t base = (size_t)(((b * 2 + h) * 2 + chunk)) * 32768;
    uint32_t off = (uint32_t)(n * 256 + ((((kk >> 3) ^ (n & 7))) << 4) + (kk & 7) * 2);
    *(__nv_bfloat16*)(g_Bhi + base + off) = hi;
    *(__nv_bfloat16*)(g_Blo + base + off) = lo;
}

// ---------------------------------------------------------------------------
__device__ __forceinline__ uint32_t smem_to_u32(const void* p) {
    uint32_t a;
    asm("{ .reg .u64 t; cvta.to.shared.u64 t, %1; cvt.u32.u64 %0, t; }" : "=r"(a) : "l"(p));
    return a;
}
#define LDSM_X4(r0, r1, r2, r3, addr) \
    asm volatile("ldmatrix.sync.aligned.m8n8.x4.shared.b16 {%0,%1,%2,%3}, [%4];" \
                 : "=r"(r0), "=r"(r1), "=r"(r2), "=r"(r3) : "r"(addr))
#define MMA_BF16(d, a0, a1, a2, a3, b0, b1) \
    asm volatile("mma.sync.aligned.m16n8k16.row.col.f32.bf16.bf16.f32 " \
                 "{%0,%1,%2,%3}, {%4,%5,%6,%7}, {%8,%9}, {%0,%1,%2,%3};" \
                 : "+f"((d)[0]), "+f"((d)[1]), "+f"((d)[2]), "+f"((d)[3]) \
                 : "r"(a0), "r"(a1), "r"(a2), "r"(a3), "r"(b0), "r"(b1))

// smem: A_hi[0,32K) A_lo[32K,64K) B_hi[64K,96K) B_lo[96K,128K)
#define S_AHI 0
#define S_ALO 32768
#define S_BHI 65536
#define S_BLO 98304
#define SMEM_TOTAL 131072

__global__ __launch_bounds__(256, 1)
void bd_hmma_kernel(const float* __restrict__ x, float* __restrict__ out) {
    extern __shared__ __align__(128) unsigned char smem[];
    const uint32_t sb = smem_to_u32(smem);

    const int tid  = threadIdx.x;
    const int wid  = tid >> 5;
    const int lane = tid & 31;
    const int wm   = wid >> 2;          // 0..1  (64-row stripe)
    const int wn   = wid & 3;           // 0..3  (32-col stripe)

    const int bid = blockIdx.x;
    const int h   = bid & 1;
    const int b   = (bid >> 1) & 15;
    const int mt  = bid >> 5;
    const int rowTile = mt * 128;
    const int kBase   = b * BSZ;
    const int colBase = b * BSZ + h * 128;

    // per-lane ldmatrix address components
    const int rA0  = wm * 64 + (lane & 15);          // A row (msub adds 16)
    const int gA   = lane >> 4;                      // k granule offset (0/1)
    const int swrA = rA0 & 7;
    const int rB0  = wn * 32 + ((lane >> 4) & 1) * 8 + (lane & 7);  // npair adds 16
    const int gB   = (lane >> 3) & 1;
    const int swrB = rB0 & 7;

    float acc[4][4][4];
    #pragma unroll
    for (int i = 0; i < 4; i++)
        #pragma unroll
        for (int j = 0; j < 4; j++)
            #pragma unroll
            for (int e = 0; e < 4; e++) acc[i][j][e] = 0.0f;

    // A-writer mapping: each thread converts 64 k-values of one row
    const int arow = tid >> 1;
    const int akq  = (tid & 1) * 64;
    const float* xrow = x + (size_t)(rowTile + arow) * LAYER + kBase + akq;

    const size_t imgBase = (size_t)((b * 2 + h) * 2) * 32768;

    #pragma unroll 1
    for (int chunk = 0; chunk < 2; chunk++) {
        // ---- load B images (linear copy, pre-swizzled) ----
        {
            const float4* shi = (const float4*)(g_Bhi + imgBase + (size_t)chunk * 32768);
            const float4* slo = (const float4*)(g_Blo + imgBase + (size_t)chunk * 32768);
            float4* dhi = (float4*)(smem + S_BHI);
            float4* dlo = (float4*)(smem + S_BLO);
            #pragma unroll
            for (int i = 0; i < 8; i++) dhi[tid + i * 256] = shi[tid + i * 256];
            #pragma unroll
            for (int i = 0; i < 8; i++) dlo[tid + i * 256] = slo[tid + i * 256];
        }
        // ---- load + convert A (x) into smem hi/lo with swizzle ----
        {
            const float4* xr = (const float4*)(xrow + chunk * 128);
            #pragma unroll
            for (int j = 0; j < 16; j++) {
                float4 v = xr[j];
                int k = akq + j * 4;
                __nv_bfloat16 h0 = __float2bfloat16(v.x);
                __nv_bfloat16 h1 = __float2bfloat16(v.y);
                __nv_bfloat16 h2 = __float2bfloat16(v.z);
                __nv_bfloat16 h3 = __float2bfloat16(v.w);
                __nv_bfloat16 l0 = __float2bfloat16(v.x - __bfloat162float(h0));
                __nv_bfloat16 l1 = __float2bfloat16(v.y - __bfloat162float(h1));
                __nv_bfloat16 l2 = __float2bfloat16(v.z - __bfloat162float(h2));
                __nv_bfloat16 l3 = __float2bfloat16(v.w - __bfloat162float(h3));
                uint2 hp, lp;
                hp.x = ((uint32_t)__bfloat16_as_ushort(h1) << 16) | __bfloat16_as_ushort(h0);
                hp.y = ((uint32_t)__bfloat16_as_ushort(h3) << 16) | __bfloat16_as_ushort(h2);
                lp.x = ((uint32_t)__bfloat16_as_ushort(l1) << 16) | __bfloat16_as_ushort(l0);
                lp.y = ((uint32_t)__bfloat16_as_ushort(l3) << 16) | __bfloat16_as_ushort(l2);
                uint32_t off = (uint32_t)(arow * 256 + (((k >> 3) ^ (arow & 7)) << 4) + (k & 7) * 2);
                *(uint2*)(smem + S_AHI + off) = hp;
                *(uint2*)(smem + S_ALO + off) = lp;
            }
        }
        __syncthreads();

        // ---- MMA over 8 k16-steps ----
        #pragma unroll
        for (int ks = 0; ks < 8; ks++) {
            uint32_t ah[4][4], al[4][4], bh[2][4], bl[2][4];
            const uint32_t axor = (uint32_t)(((2 * ks + gA) ^ swrA) << 4);
            const uint32_t bxor = (uint32_t)(((2 * ks + gB) ^ swrB) << 4);
            #pragma unroll
            for (int msub = 0; msub < 4; msub++) {
                uint32_t rterm = (uint32_t)((rA0 + msub * 16) * 256);
                LDSM_X4(ah[msub][0], ah[msub][1], ah[msub][2], ah[msub][3],
                        sb + S_AHI + rterm + axor);
                LDSM_X4(al[msub][0], al[msub][1], al[msub][2], al[msub][3],
                        sb + S_ALO + rterm + axor);
            }
            #pragma unroll
            for (int np = 0; np < 2; np++) {
                uint32_t rterm = (uint32_t)((rB0 + np * 16) * 256);
                // B stored [n][k]: NON-trans ldmatrix yields the b-fragment
                LDSM_X4(bh[np][0], bh[np][1], bh[np][2], bh[np][3],
                        sb + S_BHI + rterm + bxor);
                LDSM_X4(bl[np][0], bl[np][1], bl[np][2], bl[np][3],
                        sb + S_BLO + rterm + bxor);
            }
            #pragma unroll
            for (int msub = 0; msub < 4; msub++) {
                #pragma unroll
                for (int np = 0; np < 2; np++) {
                    // nsub = np*2 : regs [0],[1] ; nsub = np*2+1 : regs [2],[3]
                    MMA_BF16(acc[msub][np * 2],     ah[msub][0], ah[msub][1], ah[msub][2], ah[msub][3], bh[np][0], bh[np][1]);
                    MMA_BF16(acc[msub][np * 2 + 1], ah[msub][0], ah[msub][1], ah[msub][2], ah[msub][3], bh[np][2], bh[np][3]);
                    MMA_BF16(acc[msub][np * 2],     ah[msub][0], ah[msub][1], ah[msub][2], ah[msub][3], bl[np][0], bl[np][1]);
                    MMA_BF16(acc[msub][np * 2 + 1], ah[msub][0], ah[msub][1], ah[msub][2], ah[msub][3], bl[np][2], bl[np][3]);
                    MMA_BF16(acc[msub][np * 2],     al[msub][0], al[msub][1], al[msub][2], al[msub][3], bh[np][0], bh[np][1]);
                    MMA_BF16(acc[msub][np * 2 + 1], al[msub][0], al[msub][1], al[msub][2], al[msub][3], bh[np][2], bh[np][3]);
                }
            }
        }
        __syncthreads();
    }

    // ---- epilogue ----
    const int g4  = lane >> 2;
    const int tig = lane & 3;
    #pragma unroll
    for (int msub = 0; msub < 4; msub++) {
        int r0 = rowTile + wm * 64 + msub * 16 + g4;
        #pragma unroll
        for (int nsub = 0; nsub < 4; nsub++) {
            int c = colBase + wn * 32 + nsub * 8 + tig * 2;
            float* o0 = out + (size_t)r0 * LAYER + c;
            float* o1 = out + (size_t)(r0 + 8) * LAYER + c;
            *(float2*)o0 = make_float2(acc[msub][nsub][0], acc[msub][nsub][1]);
            *(float2*)o1 = make_float2(acc[msub][nsub][2], acc[msub][nsub][3]);
        }
    }
}

// ---------------------------------------------------------------------------
extern "C" void kernel_launch(void* const* d_in, const int* in_sizes, int n_in,
                              void* d_out, int out_size) {
    const float* x      = (const float*)d_in[0];
    const float* blocks = (const float*)d_in[1];
    float* out = (float*)d_out;

    cudaFuncSetAttribute(bd_hmma_kernel,
                         cudaFuncAttributeMaxDynamicSharedMemorySize, SMEM_TOTAL);

    prep_b_kernel<<<4096, 256>>>(blocks);
    bd_hmma_kernel<<<64 * NBLK * 2, 256, SMEM_TOTAL>>>(x, out);
}

// round 8
// speedup vs baseline: 2.1762x; 1.3292x over previous
#include <cuda_runtime.h>
#include <cuda_bf16.h>
#include <cstdint>

// out[8192,4096] = x[8192,4096] @ tanh(block_diag), 16 blocks of 256x256.
// bf16-split warp mma.sync: C = Ah*Bh + Ah*Bl + Al*Bh.
// R5: 512 threads (16 warps, 32x32 warp tile), K chunked by 64,
//     cp.async double-buffered B, x LDG->regs overlapped with MMA.
// (R7 = identical resubmit of R5; round 6 bench was an infra failure.)

#define NROWS   8192
#define LAYER   4096
#define NBLK    16
#define BSZ     256

// ---------------------------------------------------------------------------
// Precomputed B images: tanh'd, bf16-split, pre-swizzled for ldmatrix.
// Image = one (block, half, kchunk64): [n=128][k=64] bf16, 128B rows,
// off = n*128 + (((k>>3) ^ (n&7))<<4) + (k&7)*2.   16KB per image.
// 16 blk * 2 half * 4 chunk = 128 images * 16KB = 2MB per array.
__device__ __align__(16) unsigned char g_Bhi[NBLK * 2 * 4 * 16384];
__device__ __align__(16) unsigned char g_Blo[NBLK * 2 * 4 * 16384];

__global__ void prep_b_kernel(const float* __restrict__ blocks) {
    unsigned g = blockIdx.x * blockDim.x + threadIdx.x;   // 1M threads
    int n = g & 127;            // out-col within half
    int k = (g >> 7) & 255;     // K within block
    int h = (g >> 15) & 1;      // N half
    int b = g >> 16;            // block
    float v = tanhf(blocks[(size_t)(b * BSZ + k) * LAYER + b * BSZ + h * 128 + n]);
    __nv_bfloat16 hi = __float2bfloat16(v);
    __nv_bfloat16 lo = __float2bfloat16(v - __bfloat162float(hi));
    int chunk = k >> 6, kk = k & 63;
    size_t base = (size_t)((b * 2 + h) * 4 + chunk) * 16384;
    uint32_t off = (uint32_t)(n * 128 + ((((kk >> 3) ^ (n & 7))) << 4) + (kk & 7) * 2);
    *(__nv_bfloat16*)(g_Bhi + base + off) = hi;
    *(__nv_bfloat16*)(g_Blo + base + off) = lo;
}

// ---------------------------------------------------------------------------
__device__ __forceinline__ uint32_t smem_to_u32(const void* p) {
    uint32_t a;
    asm("{ .reg .u64 t; cvta.to.shared.u64 t, %1; cvt.u32.u64 %0, t; }" : "=r"(a) : "l"(p));
    return a;
}
__device__ __forceinline__ void cp_async16(uint32_t saddr, const void* g) {
    asm volatile("cp.async.cg.shared.global [%0], [%1], 16;" :: "r"(saddr), "l"(g));
}
#define CP_COMMIT() asm volatile("cp.async.commit_group;" ::: "memory")
#define CP_WAIT0()  asm volatile("cp.async.wait_group 0;" ::: "memory")
#define LDSM_X4(r0, r1, r2, r3, addr) \
    asm volatile("ldmatrix.sync.aligned.m8n8.x4.shared.b16 {%0,%1,%2,%3}, [%4];" \
                 : "=r"(r0), "=r"(r1), "=r"(r2), "=r"(r3) : "r"(addr))
#define MMA_BF16(d, a0, a1, a2, a3, b0, b1) \
    asm volatile("mma.sync.aligned.m16n8k16.row.col.f32.bf16.bf16.f32 " \
                 "{%0,%1,%2,%3}, {%4,%5,%6,%7}, {%8,%9}, {%0,%1,%2,%3};" \
                 : "+f"((d)[0]), "+f"((d)[1]), "+f"((d)[2]), "+f"((d)[3]) \
                 : "r"(a0), "r"(a1), "r"(a2), "r"(a3), "r"(b0), "r"(b1))

// stage layout (64KB per stage, 2 stages = 128KB):
//   +0      A_hi  16KB   [row 0..127][k 0..63]
//   +16384  A_lo  16KB
//   +32768  B_hi  16KB   [n 0..127][k 0..63]
//   +49152  B_lo  16KB
#define STAGE_BYTES 65536
#define O_ALO 16384
#define O_BHI 32768
#define O_BLO 49152
#define SMEM_TOTAL (2 * STAGE_BYTES)

__global__ __launch_bounds__(512, 1)
void bd_hmma_kernel(const float* __restrict__ x, float* __restrict__ out) {
    extern __shared__ __align__(128) unsigned char smem[];
    const uint32_t sb = smem_to_u32(smem);

    const int tid  = threadIdx.x;
    const int wid  = tid >> 5;
    const int lane = tid & 31;
    const int wm   = wid >> 2;          // 0..3  (32-row stripe)
    const int wn   = wid & 3;           // 0..3  (32-col stripe)

    const int bid = blockIdx.x;
    const int h   = bid & 1;
    const int b   = (bid >> 1) & 15;
    const int mt  = bid >> 5;
    const int rowTile = mt * 128;
    const int kBase   = b * BSZ;
    const int colBase = b * BSZ + h * 128;

    // ldmatrix per-lane address components
    const int rA0  = wm * 32 + (lane & 15);
    const int gA   = lane >> 4;
    const int swrA = rA0 & 7;
    const int rB0  = wn * 32 + ((lane >> 4) & 1) * 8 + (lane & 7);
    const int gB   = (lane >> 3) & 1;
    const int swrB = rB0 & 7;

    float acc[2][4][4];
    #pragma unroll
    for (int i = 0; i < 2; i++)
        #pragma unroll
        for (int j = 0; j < 4; j++)
            #pragma unroll
            for (int e = 0; e < 4; e++) acc[i][j][e] = 0.0f;

    // A writer mapping: 4 threads per row, 16 k-values each
    const int arow = tid >> 2;
    const int kseg = (tid & 3) * 16;
    const float* xrow = x + (size_t)(rowTile + arow) * LAYER + kBase + kseg;

    const size_t imgBase = (size_t)((b * 2 + h) * 4) * 16384;

    float4 xv0, xv1, xv2, xv3;

    // ---- helpers as macros (keep everything inlined/unrolled) ----
#define LOAD_B(c, s) do { \
        uint32_t dhi = sb + (s) * STAGE_BYTES + O_BHI + tid * 16; \
        uint32_t dlo = sb + (s) * STAGE_BYTES + O_BLO + tid * 16; \
        const unsigned char* shi = g_Bhi + imgBase + (size_t)(c) * 16384 + tid * 16; \
        const unsigned char* slo = g_Blo + imgBase + (size_t)(c) * 16384 + tid * 16; \
        cp_async16(dhi,        shi); \
        cp_async16(dhi + 8192, shi + 8192); \
        cp_async16(dlo,        slo); \
        cp_async16(dlo + 8192, slo + 8192); \
    } while (0)

#define LOAD_X(c) do { \
        const float4* p = (const float4*)(xrow + (c) * 64); \
        xv0 = p[0]; xv1 = p[1]; xv2 = p[2]; xv3 = p[3]; \
    } while (0)

#define STORE_A(s) do { \
        float4 vv[4] = {xv0, xv1, xv2, xv3}; \
        _Pragma("unroll") \
        for (int j = 0; j < 4; j++) { \
            float4 v = vv[j]; \
            int k = kseg + j * 4; \
            __nv_bfloat16 h0 = __float2bfloat16(v.x); \
            __nv_bfloat16 h1 = __float2bfloat16(v.y); \
            __nv_bfloat16 h2 = __float2bfloat16(v.z); \
            __nv_bfloat16 h3 = __float2bfloat16(v.w); \
            __nv_bfloat16 l0 = __float2bfloat16(v.x - __bfloat162float(h0)); \
            __nv_bfloat16 l1 = __float2bfloat16(v.y - __bfloat162float(h1)); \
            __nv_bfloat16 l2 = __float2bfloat16(v.z - __bfloat162float(h2)); \
            __nv_bfloat16 l3 = __float2bfloat16(v.w - __bfloat162float(h3)); \
            uint2 hp, lp; \
            hp.x = ((uint32_t)__bfloat16_as_ushort(h1) << 16) | __bfloat16_as_ushort(h0); \
            hp.y = ((uint32_t)__bfloat16_as_ushort(h3) << 16) | __bfloat16_as_ushort(h2); \
            lp.x = ((uint32_t)__bfloat16_as_ushort(l1) << 16) | __bfloat16_as_ushort(l0); \
            lp.y = ((uint32_t)__bfloat16_as_ushort(l3) << 16) | __bfloat16_as_ushort(l2); \
            uint32_t off = (uint32_t)(arow * 128 + (((k >> 3) ^ (arow & 7)) << 4) + (k & 7) * 2); \
            *(uint2*)(smem + (s) * STAGE_BYTES + off) = hp; \
            *(uint2*)(smem + (s) * STAGE_BYTES + O_ALO + off) = lp; \
        } \
    } while (0)

#define MMA_CHUNK(s) do { \
        const uint32_t base = sb + (s) * STAGE_BYTES; \
        _Pragma("unroll") \
        for (int ks = 0; ks < 4; ks++) { \
            uint32_t ah[2][4], al[2][4], bh[2][4], bl[2][4]; \
            const uint32_t axor = (uint32_t)(((2 * ks + gA) ^ swrA) << 4); \
            const uint32_t bxor = (uint32_t)(((2 * ks + gB) ^ swrB) << 4); \
            _Pragma("unroll") \
            for (int msub = 0; msub < 2; msub++) { \
                uint32_t rterm = (uint32_t)((rA0 + msub * 16) * 128); \
                LDSM_X4(ah[msub][0], ah[msub][1], ah[msub][2], ah[msub][3], base + rterm + axor); \
                LDSM_X4(al[msub][0], al[msub][1], al[msub][2], al[msub][3], base + O_ALO + rterm + axor); \
            } \
            _Pragma("unroll") \
            for (int np = 0; np < 2; np++) { \
                uint32_t rterm = (uint32_t)((rB0 + np * 16) * 128); \
                LDSM_X4(bh[np][0], bh[np][1], bh[np][2], bh[np][3], base + O_BHI + rterm + bxor); \
                LDSM_X4(bl[np][0], bl[np][1], bl[np][2], bl[np][3], base + O_BLO + rterm + bxor); \
            } \
            _Pragma("unroll") \
            for (int msub = 0; msub < 2; msub++) { \
                _Pragma("unroll") \
                for (int np = 0; np < 2; np++) { \
                    MMA_BF16(acc[msub][np * 2],     ah[msub][0], ah[msub][1], ah[msub][2], ah[msub][3], bh[np][0], bh[np][1]); \
                    MMA_BF16(acc[msub][np * 2 + 1], ah[msub][0], ah[msub][1], ah[msub][2], ah[msub][3], bh[np][2], bh[np][3]); \
                    MMA_BF16(acc[msub][np * 2],     ah[msub][0], ah[msub][1], ah[msub][2], ah[msub][3], bl[np][0], bl[np][1]); \
                    MMA_BF16(acc[msub][np * 2 + 1], ah[msub][0], ah[msub][1], ah[msub][2], ah[msub][3], bl[np][2], bl[np][3]); \
                    MMA_BF16(acc[msub][np * 2],     al[msub][0], al[msub][1], al[msub][2], al[msub][3], bh[np][0], bh[np][1]); \
                    MMA_BF16(acc[msub][np * 2 + 1], al[msub][0], al[msub][1], al[msub][2], al[msub][3], bh[np][2], bh[np][3]); \
                } \
            } \
        } \
    } while (0)

    // ---- prologue: stage chunk 0 ----
    LOAD_B(0, 0);
    CP_COMMIT();
    LOAD_X(0);
    STORE_A(0);
    CP_WAIT0();
    __syncthreads();

    // ---- main pipeline over 4 k-chunks ----
    #pragma unroll
    for (int c = 0; c < 4; c++) {
        const int s  = c & 1;
        const int ns = s ^ 1;
        if (c < 3) {
            LOAD_B(c + 1, ns);
            CP_COMMIT();
            LOAD_X(c + 1);
        }
        MMA_CHUNK(s);
        if (c < 3) {
            STORE_A(ns);
            CP_WAIT0();
        }
        __syncthreads();
    }

    // ---- epilogue ----
    const int g4  = lane >> 2;
    const int tig = lane & 3;
    #pragma unroll
    for (int msub = 0; msub < 2; msub++) {
        int r0 = rowTile + wm * 32 + msub * 16 + g4;
        #pragma unroll
        for (int nsub = 0; nsub < 4; nsub++) {
            int c = colBase + wn * 32 + nsub * 8 + tig * 2;
            float* o0 = out + (size_t)r0 * LAYER + c;
            float* o1 = out + (size_t)(r0 + 8) * LAYER + c;
            *(float2*)o0 = make_float2(acc[msub][nsub][0], acc[msub][nsub][1]);
            *(float2*)o1 = make_float2(acc[msub][nsub][2], acc[msub][nsub][3]);
        }
    }
#undef LOAD_B
#undef LOAD_X
#undef STORE_A
#undef MMA_CHUNK
}

// ---------------------------------------------------------------------------
extern "C" void kernel_launch(void* const* d_in, const int* in_sizes, int n_in,
                              void* d_out, int out_size) {
    const float* x      = (const float*)d_in[0];
    const float* blocks = (const float*)d_in[1];
    float* out = (float*)d_out;

    cudaFuncSetAttribute(bd_hmma_kernel,
                         cudaFuncAttributeMaxDynamicSharedMemorySize, SMEM_TOTAL);

    prep_b_kernel<<<4096, 256>>>(blocks);
    bd_hmma_kernel<<<64 * NBLK * 2, 512, SMEM_TOTAL>>>(x, out);
}

// round 9
// speedup vs baseline: 2.4906x; 1.1445x over previous
#include <cuda_runtime.h>
#include <cuda_bf16.h>
#include <cstdint>

// out[8192,4096] = x[8192,4096] @ tanh(block_diag), 16 blocks of 256x256.
// bf16-split warp mma.sync: C = Ah*Bh + Ah*Bl + Al*Bh.
// R8: CTA tile 128x256 (full block width), warp tile 32x64, 512 threads,
//     cp.async double-buffered B, K chunked by 64.

#define NROWS   8192
#define LAYER   4096
#define NBLK    16
#define BSZ     256

// ---------------------------------------------------------------------------
// Precomputed B images: tanh'd, bf16-split, pre-swizzled for ldmatrix.
// Image = one (block, kchunk64): [n=256][k=64] bf16, 128B rows, 32KB.
// off = n*128 + (((k>>3) ^ (n&7))<<4) + (k&7)*2.
// 16 blk * 4 chunk = 64 images * 32KB = 2MB per array.
__device__ __align__(16) unsigned char g_Bhi[NBLK * 4 * 32768];
__device__ __align__(16) unsigned char g_Blo[NBLK * 4 * 32768];

__global__ void prep_b_kernel(const float* __restrict__ blocks) {
    unsigned g = blockIdx.x * blockDim.x + threadIdx.x;   // 1M threads
    int n = g & 255;            // out-col within block
    int k = (g >> 8) & 255;     // K within block
    int b = g >> 16;            // block
    float v = tanhf(blocks[(size_t)(b * BSZ + k) * LAYER + b * BSZ + n]);
    __nv_bfloat16 hi = __float2bfloat16(v);
    __nv_bfloat16 lo = __float2bfloat16(v - __bfloat162float(hi));
    int chunk = k >> 6, kk = k & 63;
    size_t base = (size_t)(b * 4 + chunk) * 32768;
    uint32_t off = (uint32_t)(n * 128 + ((((kk >> 3) ^ (n & 7))) << 4) + (kk & 7) * 2);
    *(__nv_bfloat16*)(g_Bhi + base + off) = hi;
    *(__nv_bfloat16*)(g_Blo + base + off) = lo;
}

// ---------------------------------------------------------------------------
__device__ __forceinline__ uint32_t smem_to_u32(const void* p) {
    uint32_t a;
    asm("{ .reg .u64 t; cvta.to.shared.u64 t, %1; cvt.u32.u64 %0, t; }" : "=r"(a) : "l"(p));
    return a;
}
__device__ __forceinline__ void cp_async16(uint32_t saddr, const void* g) {
    asm volatile("cp.async.cg.shared.global [%0], [%1], 16;" :: "r"(saddr), "l"(g));
}
#define CP_COMMIT() asm volatile("cp.async.commit_group;" ::: "memory")
#define CP_WAIT0()  asm volatile("cp.async.wait_group 0;" ::: "memory")
#define LDSM_X4(r0, r1, r2, r3, addr) \
    asm volatile("ldmatrix.sync.aligned.m8n8.x4.shared.b16 {%0,%1,%2,%3}, [%4];" \
                 : "=r"(r0), "=r"(r1), "=r"(r2), "=r"(r3) : "r"(addr))
#define MMA_BF16(d, a0, a1, a2, a3, b0, b1) \
    asm volatile("mma.sync.aligned.m16n8k16.row.col.f32.bf16.bf16.f32 " \
                 "{%0,%1,%2,%3}, {%4,%5,%6,%7}, {%8,%9}, {%0,%1,%2,%3};" \
                 : "+f"((d)[0]), "+f"((d)[1]), "+f"((d)[2]), "+f"((d)[3]) \
                 : "r"(a0), "r"(a1), "r"(a2), "r"(a3), "r"(b0), "r"(b1))

// stage layout (96KB per stage, 2 stages = 192KB):
//   +0      A_hi 16KB  [row 0..127][k 0..63]
//   +16384  A_lo 16KB
//   +32768  B_hi 32KB  [n 0..255][k 0..63]
//   +65536  B_lo 32KB
#define STAGE_BYTES 98304
#define O_ALO 16384
#define O_BHI 32768
#define O_BLO 65536
#define SMEM_TOTAL (2 * STAGE_BYTES)

__global__ __launch_bounds__(512, 1)
void bd_hmma_kernel(const float* __restrict__ x, float* __restrict__ out) {
    extern __shared__ __align__(128) unsigned char smem[];
    const uint32_t sb = smem_to_u32(smem);

    const int tid  = threadIdx.x;
    const int wid  = tid >> 5;
    const int lane = tid & 31;
    const int wm   = wid >> 2;          // 0..3  (32-row stripe)
    const int wn   = wid & 3;           // 0..3  (64-col stripe)

    const int bid = blockIdx.x;
    const int b   = bid & 15;
    const int mt  = bid >> 4;
    const int rowTile = mt * 128;
    const int kBase   = b * BSZ;
    const int colBase = b * BSZ;

    // ldmatrix per-lane address components
    const int rA0  = wm * 32 + (lane & 15);
    const int gA   = lane >> 4;
    const int swrA = rA0 & 7;
    const int rB0  = wn * 64 + ((lane >> 4) & 1) * 8 + (lane & 7);  // np adds 16
    const int gB   = (lane >> 3) & 1;
    const int swrB = rB0 & 7;

    float acc[2][8][4];
    #pragma unroll
    for (int i = 0; i < 2; i++)
        #pragma unroll
        for (int j = 0; j < 8; j++)
            #pragma unroll
            for (int e = 0; e < 4; e++) acc[i][j][e] = 0.0f;

    // A writer mapping: 4 threads per row, 16 k-values each
    const int arow = tid >> 2;
    const int kseg = (tid & 3) * 16;
    const float* xrow = x + (size_t)(rowTile + arow) * LAYER + kBase + kseg;

    const size_t imgBase = (size_t)(b * 4) * 32768;

    float4 xv0, xv1, xv2, xv3;

#define LOAD_B(c, s) do { \
        uint32_t dhi = sb + (s) * STAGE_BYTES + O_BHI + tid * 16; \
        uint32_t dlo = sb + (s) * STAGE_BYTES + O_BLO + tid * 16; \
        const unsigned char* shi = g_Bhi + imgBase + (size_t)(c) * 32768 + tid * 16; \
        const unsigned char* slo = g_Blo + imgBase + (size_t)(c) * 32768 + tid * 16; \
        cp_async16(dhi,         shi); \
        cp_async16(dhi +  8192, shi +  8192); \
        cp_async16(dhi + 16384, shi + 16384); \
        cp_async16(dhi + 24576, shi + 24576); \
        cp_async16(dlo,         slo); \
        cp_async16(dlo +  8192, slo +  8192); \
        cp_async16(dlo + 16384, slo + 16384); \
        cp_async16(dlo + 24576, slo + 24576); \
    } while (0)

#define LOAD_X(c) do { \
        const float4* p = (const float4*)(xrow + (c) * 64); \
        xv0 = p[0]; xv1 = p[1]; xv2 = p[2]; xv3 = p[3]; \
    } while (0)

#define STORE_A(s) do { \
        float4 vv[4] = {xv0, xv1, xv2, xv3}; \
        _Pragma("unroll") \
        for (int j = 0; j < 4; j++) { \
            float4 v = vv[j]; \
            int k = kseg + j * 4; \
            __nv_bfloat16 h0 = __float2bfloat16(v.x); \
            __nv_bfloat16 h1 = __float2bfloat16(v.y); \
            __nv_bfloat16 h2 = __float2bfloat16(v.z); \
            __nv_bfloat16 h3 = __float2bfloat16(v.w); \
            __nv_bfloat16 l0 = __float2bfloat16(v.x - __bfloat162float(h0)); \
            __nv_bfloat16 l1 = __float2bfloat16(v.y - __bfloat162float(h1)); \
            __nv_bfloat16 l2 = __float2bfloat16(v.z - __bfloat162float(h2)); \
            __nv_bfloat16 l3 = __float2bfloat16(v.w - __bfloat162float(h3)); \
            uint2 hp, lp; \
            hp.x = ((uint32_t)__bfloat16_as_ushort(h1) << 16) | __bfloat16_as_ushort(h0); \
            hp.y = ((uint32_t)__bfloat16_as_ushort(h3) << 16) | __bfloat16_as_ushort(h2); \
            lp.x = ((uint32_t)__bfloat16_as_ushort(l1) << 16) | __bfloat16_as_ushort(l0); \
            lp.y = ((uint32_t)__bfloat16_as_ushort(l3) << 16) | __bfloat16_as_ushort(l2); \
            uint32_t off = (uint32_t)(arow * 128 + (((k >> 3) ^ (arow & 7)) << 4) + (k & 7) * 2); \
            *(uint2*)(smem + (s) * STAGE_BYTES + off) = hp; \
            *(uint2*)(smem + (s) * STAGE_BYTES + O_ALO + off) = lp; \
        } \
    } while (0)

#define MMA_CHUNK(s) do { \
        const uint32_t base = sb + (s) * STAGE_BYTES; \
        _Pragma("unroll") \
        for (int ks = 0; ks < 4; ks++) { \
            uint32_t ah[2][4], al[2][4]; \
            const uint32_t axor = (uint32_t)(((2 * ks + gA) ^ swrA) << 4); \
            const uint32_t bxor = (uint32_t)(((2 * ks + gB) ^ swrB) << 4); \
            _Pragma("unroll") \
            for (int msub = 0; msub < 2; msub++) { \
                uint32_t rterm = (uint32_t)((rA0 + msub * 16) * 128); \
                LDSM_X4(ah[msub][0], ah[msub][1], ah[msub][2], ah[msub][3], base + rterm + axor); \
                LDSM_X4(al[msub][0], al[msub][1], al[msub][2], al[msub][3], base + O_ALO + rterm + axor); \
            } \
            _Pragma("unroll") \
            for (int nh = 0; nh < 2; nh++) { \
                uint32_t bh[2][4], bl[2][4]; \
                _Pragma("unroll") \
                for (int npl = 0; npl < 2; npl++) { \
                    uint32_t rterm = (uint32_t)((rB0 + (nh * 2 + npl) * 16) * 128); \
                    LDSM_X4(bh[npl][0], bh[npl][1], bh[npl][2], bh[npl][3], base + O_BHI + rterm + bxor); \
                    LDSM_X4(bl[npl][0], bl[npl][1], bl[npl][2], bl[npl][3], base + O_BLO + rterm + bxor); \
                } \
                _Pragma("unroll") \
                for (int msub = 0; msub < 2; msub++) { \
                    _Pragma("unroll") \
                    for (int npl = 0; npl < 2; npl++) { \
                        const int nb = (nh * 2 + npl) * 2; \
                        MMA_BF16(acc[msub][nb],     ah[msub][0], ah[msub][1], ah[msub][2], ah[msub][3], bh[npl][0], bh[npl][1]); \
                        MMA_BF16(acc[msub][nb + 1], ah[msub][0], ah[msub][1], ah[msub][2], ah[msub][3], bh[npl][2], bh[npl][3]); \
                        MMA_BF16(acc[msub][nb],     ah[msub][0], ah[msub][1], ah[msub][2], ah[msub][3], bl[npl][0], bl[npl][1]); \
                        MMA_BF16(acc[msub][nb + 1], ah[msub][0], ah[msub][1], ah[msub][2], ah[msub][3], bl[npl][2], bl[npl][3]); \
                        MMA_BF16(acc[msub][nb],     al[msub][0], al[msub][1], al[msub][2], al[msub][3], bh[npl][0], bh[npl][1]); \
                        MMA_BF16(acc[msub][nb + 1], al[msub][0], al[msub][1], al[msub][2], al[msub][3], bh[npl][2], bh[npl][3]); \
                    } \
                } \
            } \
        } \
    } while (0)

    // ---- prologue: stage chunk 0 ----
    LOAD_B(0, 0);
    CP_COMMIT();
    LOAD_X(0);
    STORE_A(0);
    CP_WAIT0();
    __syncthreads();

    // ---- main pipeline over 4 k-chunks ----
    #pragma unroll
    for (int c = 0; c < 4; c++) {
        const int s  = c & 1;
        const int ns = s ^ 1;
        if (c < 3) {
            LOAD_B(c + 1, ns);
            CP_COMMIT();
            LOAD_X(c + 1);
        }
        MMA_CHUNK(s);
        if (c < 3) {
            STORE_A(ns);
            CP_WAIT0();
        }
        __syncthreads();
    }

    // ---- epilogue ----
    const int g4  = lane >> 2;
    const int tig = lane & 3;
    #pragma unroll
    for (int msub = 0; msub < 2; msub++) {
        int r0 = rowTile + wm * 32 + msub * 16 + g4;
        #pragma unroll
        for (int nsub = 0; nsub < 8; nsub++) {
            int c = colBase + wn * 64 + nsub * 8 + tig * 2;
            float* o0 = out + (size_t)r0 * LAYER + c;
            float* o1 = out + (size_t)(r0 + 8) * LAYER + c;
            *(float2*)o0 = make_float2(acc[msub][nsub][0], acc[msub][nsub][1]);
            *(float2*)o1 = make_float2(acc[msub][nsub][2], acc[msub][nsub][3]);
        }
    }
#undef LOAD_B
#undef LOAD_X
#undef STORE_A
#undef MMA_CHUNK
}

// ---------------------------------------------------------------------------
extern "C" void kernel_launch(void* const* d_in, const int* in_sizes, int n_in,
                              void* d_out, int out_size) {
    const float* x      = (const float*)d_in[0];
    const float* blocks = (const float*)d_in[1];
    float* out = (float*)d_out;

    cudaFuncSetAttribute(bd_hmma_kernel,
                         cudaFuncAttributeMaxDynamicSharedMemorySize, SMEM_TOTAL);

    prep_b_kernel<<<4096, 256>>>(blocks);
    bd_hmma_kernel<<<64 * NBLK, 512, SMEM_TOTAL>>>(x, out);
}

// round 10
// speedup vs baseline: 3.3724x; 1.3540x over previous
#include <cuda_runtime.h>
#include <cuda_bf16.h>
#include <cstdint>

// out[8192,4096] = x[8192,4096] @ tanh(block_diag), 16 blocks of 256x256.
// R9: single-pass TF32 mma.sync (m16n8k8). CTA tile 128x256, warp 32x64,
//     512 threads, cp.async double-buffered B, K chunked by 64.
// tf32 fragments loaded with b16 ldmatrix (tf32 tile viewed as 2x-wide b16).

#define NROWS   8192
#define LAYER   4096
#define NBLK    16
#define BSZ     256

// ---------------------------------------------------------------------------
// Precomputed B images: tanh'd, tf32, pre-swizzled.
// Image = one (block, kchunk64): [n=256][k=64 tf32], 256B rows, 64KB.
// granule g = kk>>2 (16B = 4 tf32); off = n*256 + ((g ^ (n&7))<<4) + (kk&3)*4.
// 16 blk * 4 chunk = 64 images * 64KB = 4MB.
__device__ __align__(16) unsigned char g_Btf[NBLK * 4 * 65536];

__global__ void prep_b_kernel(const float* __restrict__ blocks) {
    unsigned g = blockIdx.x * blockDim.x + threadIdx.x;   // 1M threads
    int n = g & 255;            // out-col within block
    int k = (g >> 8) & 255;     // K within block
    int b = g >> 16;            // block
    float v = tanhf(blocks[(size_t)(b * BSZ + k) * LAYER + b * BSZ + n]);
    uint32_t t;
    asm("cvt.rna.tf32.f32 %0, %1;" : "=r"(t) : "f"(v));
    int chunk = k >> 6, kk = k & 63;
    size_t base = (size_t)(b * 4 + chunk) * 65536;
    uint32_t off = (uint32_t)(n * 256 + (((kk >> 2) ^ (n & 7)) << 4) + (kk & 3) * 4);
    *(uint32_t*)(g_Btf + base + off) = t;
}

// ---------------------------------------------------------------------------
__device__ __forceinline__ uint32_t smem_to_u32(const void* p) {
    uint32_t a;
    asm("{ .reg .u64 t; cvta.to.shared.u64 t, %1; cvt.u32.u64 %0, t; }" : "=r"(a) : "l"(p));
    return a;
}
__device__ __forceinline__ void cp_async16(uint32_t saddr, const void* g) {
    asm volatile("cp.async.cg.shared.global [%0], [%1], 16;" :: "r"(saddr), "l"(g));
}
__device__ __forceinline__ uint32_t f2tf32(float f) {
    uint32_t t;
    asm("cvt.rna.tf32.f32 %0, %1;" : "=r"(t) : "f"(f));
    return t;
}
#define CP_COMMIT() asm volatile("cp.async.commit_group;" ::: "memory")
#define CP_WAIT0()  asm volatile("cp.async.wait_group 0;" ::: "memory")
#define LDSM_X4(r0, r1, r2, r3, addr) \
    asm volatile("ldmatrix.sync.aligned.m8n8.x4.shared.b16 {%0,%1,%2,%3}, [%4];" \
                 : "=r"(r0), "=r"(r1), "=r"(r2), "=r"(r3) : "r"(addr))
#define MMA_TF32(d, a0, a1, a2, a3, b0, b1) \
    asm volatile("mma.sync.aligned.m16n8k8.row.col.f32.tf32.tf32.f32 " \
                 "{%0,%1,%2,%3}, {%4,%5,%6,%7}, {%8,%9}, {%0,%1,%2,%3};" \
                 : "+f"((d)[0]), "+f"((d)[1]), "+f"((d)[2]), "+f"((d)[3]) \
                 : "r"(a0), "r"(a1), "r"(a2), "r"(a3), "r"(b0), "r"(b1))

// stage layout (96KB per stage, 2 stages = 192KB):
//   +0      A 32KB  [row 0..127][k 0..63 tf32]  256B rows, swizzled
//   +32768  B 64KB  [n 0..255][k 0..63 tf32]    256B rows, swizzled
#define STAGE_BYTES 98304
#define O_B 32768
#define SMEM_TOTAL (2 * STAGE_BYTES)

__global__ __launch_bounds__(512, 1)
void bd_mma_kernel(const float* __restrict__ x, float* __restrict__ out) {
    extern __shared__ __align__(128) unsigned char smem[];
    const uint32_t sb = smem_to_u32(smem);

    const int tid  = threadIdx.x;
    const int wid  = tid >> 5;
    const int lane = tid & 31;
    const int wm   = wid >> 2;          // 0..3  (32-row stripe)
    const int wn   = wid & 3;           // 0..3  (64-col stripe)

    const int bid = blockIdx.x;
    const int b   = bid & 15;
    const int mt  = bid >> 4;
    const int rowTile = mt * 128;
    const int kBase   = b * BSZ;
    const int colBase = b * BSZ;

    // ldmatrix per-lane address components (granule = 16B = 4 tf32)
    const int rA0  = wm * 32 + (lane & 15);          // + msub*16
    const int gA   = lane >> 4;                      // 0/1
    const int swrA = rA0 & 7;
    const int rB0  = wn * 64 + ((lane >> 4) & 1) * 8 + (lane & 7);  // + np*16
    const int gB   = (lane >> 3) & 1;
    const int swrB = rB0 & 7;

    float acc[2][8][4];
    #pragma unroll
    for (int i = 0; i < 2; i++)
        #pragma unroll
        for (int j = 0; j < 8; j++)
            #pragma unroll
            for (int e = 0; e < 4; e++) acc[i][j][e] = 0.0f;

    // A writer mapping: 4 threads per row, 16 k-values each
    const int arow = tid >> 2;
    const int kseg = (tid & 3) * 16;
    const float* xrow = x + (size_t)(rowTile + arow) * LAYER + kBase + kseg;

    const size_t imgBase = (size_t)(b * 4) * 65536;

    float4 xv0, xv1, xv2, xv3;

#define LOAD_B(c, s) do { \
        uint32_t dst = sb + (s) * STAGE_BYTES + O_B + tid * 16; \
        const unsigned char* src = g_Btf + imgBase + (size_t)(c) * 65536 + tid * 16; \
        _Pragma("unroll") \
        for (int i = 0; i < 8; i++) \
            cp_async16(dst + i * 8192, src + i * 8192); \
    } while (0)

#define LOAD_X(c) do { \
        const float4* p = (const float4*)(xrow + (c) * 64); \
        xv0 = p[0]; xv1 = p[1]; xv2 = p[2]; xv3 = p[3]; \
    } while (0)

#define STORE_A(s) do { \
        float4 vv[4] = {xv0, xv1, xv2, xv3}; \
        _Pragma("unroll") \
        for (int j = 0; j < 4; j++) { \
            float4 v = vv[j]; \
            int gidx = (kseg >> 2) + j;          /* granule index 0..15 */ \
            uint4 tv; \
            tv.x = f2tf32(v.x); tv.y = f2tf32(v.y); \
            tv.z = f2tf32(v.z); tv.w = f2tf32(v.w); \
            uint32_t off = (uint32_t)(arow * 256 + ((gidx ^ (arow & 7)) << 4)); \
            *(uint4*)(smem + (s) * STAGE_BYTES + off) = tv; \
        } \
    } while (0)

#define MMA_CHUNK(s) do { \
        const uint32_t base = sb + (s) * STAGE_BYTES; \
        _Pragma("unroll") \
        for (int ks = 0; ks < 8; ks++) { \
            uint32_t a[2][4]; \
            const uint32_t axor = (uint32_t)(((2 * ks + gA) ^ swrA) << 4); \
            const uint32_t bxor = (uint32_t)(((2 * ks + gB) ^ swrB) << 4); \
            _Pragma("unroll") \
            for (int msub = 0; msub < 2; msub++) { \
                uint32_t rterm = (uint32_t)((rA0 + msub * 16) * 256); \
                LDSM_X4(a[msub][0], a[msub][1], a[msub][2], a[msub][3], \
                        base + rterm + axor); \
            } \
            _Pragma("unroll") \
            for (int np = 0; np < 4; np++) { \
                uint32_t bb[4]; \
                uint32_t rterm = (uint32_t)((rB0 + np * 16) * 256); \
                LDSM_X4(bb[0], bb[1], bb[2], bb[3], base + O_B + rterm + bxor); \
                _Pragma("unroll") \
                for (int msub = 0; msub < 2; msub++) { \
                    MMA_TF32(acc[msub][np * 2],     a[msub][0], a[msub][1], a[msub][2], a[msub][3], bb[0], bb[1]); \
                    MMA_TF32(acc[msub][np * 2 + 1], a[msub][0], a[msub][1], a[msub][2], a[msub][3], bb[2], bb[3]); \
                } \
            } \
        } \
    } while (0)

    // ---- prologue: stage chunk 0 ----
    LOAD_B(0, 0);
    CP_COMMIT();
    LOAD_X(0);
    STORE_A(0);
    CP_WAIT0();
    __syncthreads();

    // ---- main pipeline over 4 k-chunks ----
    #pragma unroll
    for (int c = 0; c < 4; c++) {
        const int s  = c & 1;
        const int ns = s ^ 1;
        if (c < 3) {
            LOAD_B(c + 1, ns);
            CP_COMMIT();
            LOAD_X(c + 1);
        }
        MMA_CHUNK(s);
        if (c < 3) {
            STORE_A(ns);
            CP_WAIT0();
        }
        __syncthreads();
    }

    // ---- epilogue ----
    const int g4  = lane >> 2;
    const int tig = lane & 3;
    #pragma unroll
    for (int msub = 0; msub < 2; msub++) {
        int r0 = rowTile + wm * 32 + msub * 16 + g4;
        #pragma unroll
        for (int nsub = 0; nsub < 8; nsub++) {
            int c = colBase + wn * 64 + nsub * 8 + tig * 2;
            float* o0 = out + (size_t)r0 * LAYER + c;
            float* o1 = out + (size_t)(r0 + 8) * LAYER + c;
            *(float2*)o0 = make_float2(acc[msub][nsub][0], acc[msub][nsub][1]);
            *(float2*)o1 = make_float2(acc[msub][nsub][2], acc[msub][nsub][3]);
        }
    }
#undef LOAD_B
#undef LOAD_X
#undef STORE_A
#undef MMA_CHUNK
}

// ---------------------------------------------------------------------------
extern "C" void kernel_launch(void* const* d_in, const int* in_sizes, int n_in,
                              void* d_out, int out_size) {
    const float* x      = (const float*)d_in[0];
    const float* blocks = (const float*)d_in[1];
    float* out = (float*)d_out;

    cudaFuncSetAttribute(bd_mma_kernel,
                         cudaFuncAttributeMaxDynamicSharedMemorySize, SMEM_TOTAL);

    prep_b_kernel<<<4096, 256>>>(blocks);
    bd_mma_kernel<<<64 * NBLK, 512, SMEM_TOTAL>>>(x, out);
}

// round 11
// speedup vs baseline: 4.5608x; 1.3524x over previous
#include <cuda_runtime.h>
#include <cuda_fp16.h>
#include <cstdint>

// out[8192,4096] = x[8192,4096] @ tanh(block_diag), 16 blocks of 256x256.
// R10: single-product FP16 mma.sync m16n8k16 (same mantissa as tf32 -> same
// accuracy, 2x tensor rate, half the smem traffic). CTA tile 128x256,
// warp 32x64, 512 threads, cp.async double-buffered, K chunked by 64.

#define NROWS   8192
#define LAYER   4096
#define NBLK    16
#define BSZ     256

// ---------------------------------------------------------------------------
// Precomputed B images: tanh'd fp16, pre-swizzled for ldmatrix.
// Image = one (block, kchunk64): [n=256][k=64] fp16, 128B rows, 32KB.
// off = n*128 + (((k>>3) ^ (n&7))<<4) + (k&7)*2.
// 16 blk * 4 chunk = 64 images * 32KB = 2MB.
__device__ __align__(16) unsigned char g_Bf16[NBLK * 4 * 32768];

__global__ void prep_b_kernel(const float* __restrict__ blocks) {
    unsigned g = blockIdx.x * blockDim.x + threadIdx.x;   // 1M threads
    int n = g & 255;            // out-col within block
    int k = (g >> 8) & 255;     // K within block
    int b = g >> 16;            // block
    float v = tanhf(blocks[(size_t)(b * BSZ + k) * LAYER + b * BSZ + n]);
    int chunk = k >> 6, kk = k & 63;
    size_t base = (size_t)(b * 4 + chunk) * 32768;
    uint32_t off = (uint32_t)(n * 128 + ((((kk >> 3) ^ (n & 7))) << 4) + (kk & 7) * 2);
    *(__half*)(g_Bf16 + base + off) = __float2half_rn(v);
}

// ---------------------------------------------------------------------------
__device__ __forceinline__ uint32_t smem_to_u32(const void* p) {
    uint32_t a;
    asm("{ .reg .u64 t; cvta.to.shared.u64 t, %1; cvt.u32.u64 %0, t; }" : "=r"(a) : "l"(p));
    return a;
}
__device__ __forceinline__ void cp_async16(uint32_t saddr, const void* g) {
    asm volatile("cp.async.cg.shared.global [%0], [%1], 16;" :: "r"(saddr), "l"(g));
}
#define CP_COMMIT() asm volatile("cp.async.commit_group;" ::: "memory")
#define CP_WAIT0()  asm volatile("cp.async.wait_group 0;" ::: "memory")
#define LDSM_X4(r0, r1, r2, r3, addr) \
    asm volatile("ldmatrix.sync.aligned.m8n8.x4.shared.b16 {%0,%1,%2,%3}, [%4];" \
                 : "=r"(r0), "=r"(r1), "=r"(r2), "=r"(r3) : "r"(addr))
#define MMA_F16(d, a0, a1, a2, a3, b0, b1) \
    asm volatile("mma.sync.aligned.m16n8k16.row.col.f32.f16.f16.f32 " \
                 "{%0,%1,%2,%3}, {%4,%5,%6,%7}, {%8,%9}, {%0,%1,%2,%3};" \
                 : "+f"((d)[0]), "+f"((d)[1]), "+f"((d)[2]), "+f"((d)[3]) \
                 : "r"(a0), "r"(a1), "r"(a2), "r"(a3), "r"(b0), "r"(b1))

// stage layout (48KB per stage, 2 stages = 96KB):
//   +0      A 16KB  [row 0..127][k 0..63] fp16, 128B rows, swizzled
//   +16384  B 32KB  [n 0..255][k 0..63] fp16, 128B rows, swizzled
#define STAGE_BYTES 49152
#define O_B 16384
#define SMEM_TOTAL (2 * STAGE_BYTES)

__global__ __launch_bounds__(512, 1)
void bd_mma_kernel(const float* __restrict__ x, float* __restrict__ out) {
    extern __shared__ __align__(128) unsigned char smem[];
    const uint32_t sb = smem_to_u32(smem);

    const int tid  = threadIdx.x;
    const int wid  = tid >> 5;
    const int lane = tid & 31;
    const int wm   = wid >> 2;          // 0..3  (32-row stripe)
    const int wn   = wid & 3;           // 0..3  (64-col stripe)

    const int bid = blockIdx.x;
    const int b   = bid & 15;
    const int mt  = bid >> 4;
    const int rowTile = mt * 128;
    const int kBase   = b * BSZ;
    const int colBase = b * BSZ;

    // ldmatrix per-lane address components
    const int rA0  = wm * 32 + (lane & 15);
    const int gA   = lane >> 4;
    const int swrA = rA0 & 7;
    const int rB0  = wn * 64 + ((lane >> 4) & 1) * 8 + (lane & 7);  // + np*16
    const int gB   = (lane >> 3) & 1;
    const int swrB = rB0 & 7;

    float acc[2][8][4];
    #pragma unroll
    for (int i = 0; i < 2; i++)
        #pragma unroll
        for (int j = 0; j < 8; j++)
            #pragma unroll
            for (int e = 0; e < 4; e++) acc[i][j][e] = 0.0f;

    // A writer mapping: 4 threads per row, 16 k-values each
    const int arow = tid >> 2;
    const int kseg = (tid & 3) * 16;
    const float* xrow = x + (size_t)(rowTile + arow) * LAYER + kBase + kseg;

    const size_t imgBase = (size_t)(b * 4) * 32768;

    float4 xv0, xv1, xv2, xv3;

#define LOAD_B(c, s) do { \
        uint32_t dst = sb + (s) * STAGE_BYTES + O_B + tid * 16; \
        const unsigned char* src = g_Bf16 + imgBase + (size_t)(c) * 32768 + tid * 16; \
        cp_async16(dst,         src); \
        cp_async16(dst +  8192, src +  8192); \
        cp_async16(dst + 16384, src + 16384); \
        cp_async16(dst + 24576, src + 24576); \
    } while (0)

#define LOAD_X(c) do { \
        const float4* p = (const float4*)(xrow + (c) * 64); \
        xv0 = p[0]; xv1 = p[1]; xv2 = p[2]; xv3 = p[3]; \
    } while (0)

#define STORE_A(s) do { \
        float4 vv[4] = {xv0, xv1, xv2, xv3}; \
        _Pragma("unroll") \
        for (int j = 0; j < 4; j++) { \
            float4 v = vv[j]; \
            int k = kseg + j * 4; \
            uint2 hp; \
            hp.x = ((uint32_t)__half_as_ushort(__float2half_rn(v.y)) << 16) \
                 | __half_as_ushort(__float2half_rn(v.x)); \
            hp.y = ((uint32_t)__half_as_ushort(__float2half_rn(v.w)) << 16) \
                 | __half_as_ushort(__float2half_rn(v.z)); \
            uint32_t off = (uint32_t)(arow * 128 + (((k >> 3) ^ (arow & 7)) << 4) + (k & 7) * 2); \
            *(uint2*)(smem + (s) * STAGE_BYTES + off) = hp; \
        } \
    } while (0)

#define MMA_CHUNK(s) do { \
        const uint32_t base = sb + (s) * STAGE_BYTES; \
        _Pragma("unroll") \
        for (int ks = 0; ks < 4; ks++) { \
            uint32_t a[2][4]; \
            const uint32_t axor = (uint32_t)(((2 * ks + gA) ^ swrA) << 4); \
            const uint32_t bxor = (uint32_t)(((2 * ks + gB) ^ swrB) << 4); \
            _Pragma("unroll") \
            for (int msub = 0; msub < 2; msub++) { \
                uint32_t rterm = (uint32_t)((rA0 + msub * 16) * 128); \
                LDSM_X4(a[msub][0], a[msub][1], a[msub][2], a[msub][3], \
                        base + rterm + axor); \
            } \
            _Pragma("unroll") \
            for (int np = 0; np < 4; np++) { \
                uint32_t bb[4]; \
                uint32_t rterm = (uint32_t)((rB0 + np * 16) * 128); \
                LDSM_X4(bb[0], bb[1], bb[2], bb[3], base + O_B + rterm + bxor); \
                _Pragma("unroll") \
                for (int msub = 0; msub < 2; msub++) { \
                    MMA_F16(acc[msub][np * 2],     a[msub][0], a[msub][1], a[msub][2], a[msub][3], bb[0], bb[1]); \
                    MMA_F16(acc[msub][np * 2 + 1], a[msub][0], a[msub][1], a[msub][2], a[msub][3], bb[2], bb[3]); \
                } \
            } \
        } \
    } while (0)

    // ---- prologue: stage chunk 0 ----
    LOAD_B(0, 0);
    CP_COMMIT();
    LOAD_X(0);
    STORE_A(0);
    CP_WAIT0();
    __syncthreads();

    // ---- main pipeline over 4 k-chunks ----
    #pragma unroll
    for (int c = 0; c < 4; c++) {
        const int s  = c & 1;
        const int ns = s ^ 1;
        if (c < 3) {
            LOAD_B(c + 1, ns);
            CP_COMMIT();
            LOAD_X(c + 1);
        }
        MMA_CHUNK(s);
        if (c < 3) {
            STORE_A(ns);
            CP_WAIT0();
        }
        __syncthreads();
    }

    // ---- epilogue ----
    const int g4  = lane >> 2;
    const int tig = lane & 3;
    #pragma unroll
    for (int msub = 0; msub < 2; msub++) {
        int r0 = rowTile + wm * 32 + msub * 16 + g4;
        #pragma unroll
        for (int nsub = 0; nsub < 8; nsub++) {
            int c = colBase + wn * 64 + nsub * 8 + tig * 2;
            float* o0 = out + (size_t)r0 * LAYER + c;
            float* o1 = out + (size_t)(r0 + 8) * LAYER + c;
            *(float2*)o0 = make_float2(acc[msub][nsub][0], acc[msub][nsub][1]);
            *(float2*)o1 = make_float2(acc[msub][nsub][2], acc[msub][nsub][3]);
        }
    }
#undef LOAD_B
#undef LOAD_X
#undef STORE_A
#undef MMA_CHUNK
}

// ---------------------------------------------------------------------------
extern "C" void kernel_launch(void* const* d_in, const int* in_sizes, int n_in,
                              void* d_out, int out_size) {
    const float* x      = (const float*)d_in[0];
    const float* blocks = (const float*)d_in[1];
    float* out = (float*)d_out;

    cudaFuncSetAttribute(bd_mma_kernel,
                         cudaFuncAttributeMaxDynamicSharedMemorySize, SMEM_TOTAL);

    prep_b_kernel<<<4096, 256>>>(blocks);
    bd_mma_kernel<<<64 * NBLK, 512, SMEM_TOTAL>>>(x, out);
}

// round 14
// speedup vs baseline: 4.7832x; 1.0488x over previous
#include <cuda_runtime.h>
#include <cuda_fp16.h>
#include <cstdint>

// out[8192,4096] = x[8192,4096] @ tanh(block_diag), 16 blocks of 256x256.
// R12: fp16 m16n8k16 single product. CTA 128x256, warp 32x64, 512 thr.
//      3-stage cp.async pipeline, batched LDSM, smem-staged prep kernel.
//      (R11 + fix: final MMA reads stage 0, not "stage 3")

#define NROWS   8192
#define LAYER   4096
#define NBLK    16
#define BSZ     256

// ---------------------------------------------------------------------------
// Precomputed B images: tanh'd fp16, pre-swizzled for ldmatrix.
// Image = one (block, kchunk64): [n=256][k=64] fp16, 128B rows, 32KB.
// off = n*128 + (((k>>3) ^ (n&7))<<4) + (k&7)*2.
__device__ __align__(16) unsigned char g_Bf16[NBLK * 4 * 32768];

// smem-staged prep: 128 CTAs = 16 blocks x 4 kchunks x 2 n-halves.
__global__ __launch_bounds__(256)
void prep_b_kernel(const float* __restrict__ blocks) {
    __shared__ __half T[128][72];   // row stride 144B (16B-aligned)
    const int cta = blockIdx.x;
    const int nh    = cta & 1;
    const int chunk = (cta >> 1) & 3;
    const int b     = cta >> 3;
    const int n0 = nh * 128, k0 = chunk * 64;
    const int tid = threadIdx.x;

    #pragma unroll
    for (int j = 0; j < 8; j++) {
        int idx = tid + j * 256;         // 0..2047 float4s
        int kk  = idx >> 5;              // 0..63
        int nn  = (idx & 31) * 4;        // 0..124
        const float* p = blocks + (size_t)(b * BSZ + k0 + kk) * LAYER + b * BSZ + n0 + nn;
        float4 v = *(const float4*)p;
        T[nn + 0][kk] = __float2half_rn(tanhf(v.x));
        T[nn + 1][kk] = __float2half_rn(tanhf(v.y));
        T[nn + 2][kk] = __float2half_rn(tanhf(v.z));
        T[nn + 3][kk] = __float2half_rn(tanhf(v.w));
    }
    __syncthreads();

    size_t base = (size_t)(b * 4 + chunk) * 32768;
    #pragma unroll
    for (int j = 0; j < 4; j++) {
        int idx = tid + j * 256;         // 0..1023 granules
        int n = idx >> 3;                // 0..127 within half
        int g = idx & 7;                 // k-granule
        uint4 val = *(const uint4*)&T[n][g * 8];
        int nI = n0 + n;
        uint32_t off = (uint32_t)(nI * 128 + ((g ^ (nI & 7)) << 4));
        *(uint4*)(g_Bf16 + base + off) = val;
    }
}

// ---------------------------------------------------------------------------
__device__ __forceinline__ uint32_t smem_to_u32(const void* p) {
    uint32_t a;
    asm("{ .reg .u64 t; cvta.to.shared.u64 t, %1; cvt.u32.u64 %0, t; }" : "=r"(a) : "l"(p));
    return a;
}
__device__ __forceinline__ void cp_async16(uint32_t saddr, const void* g) {
    asm volatile("cp.async.cg.shared.global [%0], [%1], 16;" :: "r"(saddr), "l"(g));
}
#define CP_COMMIT() asm volatile("cp.async.commit_group;" ::: "memory")
#define CP_WAITG(n) asm volatile("cp.async.wait_group %0;" :: "n"(n) : "memory")
#define LDSM_X4(r0, r1, r2, r3, addr) \
    asm volatile("ldmatrix.sync.aligned.m8n8.x4.shared.b16 {%0,%1,%2,%3}, [%4];" \
                 : "=r"(r0), "=r"(r1), "=r"(r2), "=r"(r3) : "r"(addr))
#define MMA_F16(d, a0, a1, a2, a3, b0, b1) \
    asm volatile("mma.sync.aligned.m16n8k16.row.col.f32.f16.f16.f32 " \
                 "{%0,%1,%2,%3}, {%4,%5,%6,%7}, {%8,%9}, {%0,%1,%2,%3};" \
                 : "+f"((d)[0]), "+f"((d)[1]), "+f"((d)[2]), "+f"((d)[3]) \
                 : "r"(a0), "r"(a1), "r"(a2), "r"(a3), "r"(b0), "r"(b1))

// stage layout (48KB per stage, 3 stages = 144KB):
//   +0      A 16KB  [row 0..127][k 0..63] fp16 swizzled
//   +16384  B 32KB  [n 0..255][k 0..63] fp16 swizzled
#define STAGE_BYTES 49152
#define O_B 16384
#define SMEM_TOTAL (3 * STAGE_BYTES)

__global__ __launch_bounds__(512, 1)
void bd_mma_kernel(const float* __restrict__ x, float* __restrict__ out) {
    extern __shared__ __align__(128) unsigned char smem[];
    const uint32_t sb = smem_to_u32(smem);

    const int tid  = threadIdx.x;
    const int wid  = tid >> 5;
    const int lane = tid & 31;
    const int wm   = wid >> 2;          // 0..3
    const int wn   = wid & 3;           // 0..3

    const int bid = blockIdx.x;
    const int b   = bid & 15;
    const int mt  = bid >> 4;
    const int rowTile = mt * 128;
    const int kBase   = b * BSZ;
    const int colBase = b * BSZ;

    const int rA0  = wm * 32 + (lane & 15);
    const int gA   = lane >> 4;
    const int swrA = rA0 & 7;
    const int rB0  = wn * 64 + ((lane >> 4) & 1) * 8 + (lane & 7);  // + np*16
    const int gB   = (lane >> 3) & 1;
    const int swrB = rB0 & 7;

    float acc[2][8][4];
    #pragma unroll
    for (int i = 0; i < 2; i++)
        #pragma unroll
        for (int j = 0; j < 8; j++)
            #pragma unroll
            for (int e = 0; e < 4; e++) acc[i][j][e] = 0.0f;

    const int arow = tid >> 2;
    const int kseg = (tid & 3) * 16;
    const float* xrow = x + (size_t)(rowTile + arow) * LAYER + kBase + kseg;

    const size_t imgBase = (size_t)(b * 4) * 32768;

    float4 xv0, xv1, xv2, xv3;

#define LOAD_B(c, s) do { \
        uint32_t dst = sb + (s) * STAGE_BYTES + O_B + tid * 16; \
        const unsigned char* src = g_Bf16 + imgBase + (size_t)(c) * 32768 + tid * 16; \
        cp_async16(dst,         src); \
        cp_async16(dst +  8192, src +  8192); \
        cp_async16(dst + 16384, src + 16384); \
        cp_async16(dst + 24576, src + 24576); \
        CP_COMMIT(); \
    } while (0)

#define LOAD_X(c) do { \
        const float4* p = (const float4*)(xrow + (c) * 64); \
        xv0 = p[0]; xv1 = p[1]; xv2 = p[2]; xv3 = p[3]; \
    } while (0)

#define STORE_A(s) do { \
        float4 vv[4] = {xv0, xv1, xv2, xv3}; \
        _Pragma("unroll") \
        for (int j = 0; j < 4; j++) { \
            float4 v = vv[j]; \
            int k = kseg + j * 4; \
            uint2 hp; \
            hp.x = ((uint32_t)__half_as_ushort(__float2half_rn(v.y)) << 16) \
                 | __half_as_ushort(__float2half_rn(v.x)); \
            hp.y = ((uint32_t)__half_as_ushort(__float2half_rn(v.w)) << 16) \
                 | __half_as_ushort(__float2half_rn(v.z)); \
            uint32_t off = (uint32_t)(arow * 128 + (((k >> 3) ^ (arow & 7)) << 4) + (k & 7) * 2); \
            *(uint2*)(smem + (s) * STAGE_BYTES + off) = hp; \
        } \
    } while (0)

// batched LDSM: all 6 fragment loads up front, then 16 MMAs
#define MMA_CHUNK(s) do { \
        const uint32_t base = sb + (s) * STAGE_BYTES; \
        _Pragma("unroll") \
        for (int ks = 0; ks < 4; ks++) { \
            uint32_t a[2][4], bb[4][4]; \
            const uint32_t axor = (uint32_t)(((2 * ks + gA) ^ swrA) << 4); \
            const uint32_t bxor = (uint32_t)(((2 * ks + gB) ^ swrB) << 4); \
            _Pragma("unroll") \
            for (int msub = 0; msub < 2; msub++) { \
                uint32_t rterm = (uint32_t)((rA0 + msub * 16) * 128); \
                LDSM_X4(a[msub][0], a[msub][1], a[msub][2], a[msub][3], \
                        base + rterm + axor); \
            } \
            _Pragma("unroll") \
            for (int np = 0; np < 4; np++) { \
                uint32_t rterm = (uint32_t)((rB0 + np * 16) * 128); \
                LDSM_X4(bb[np][0], bb[np][1], bb[np][2], bb[np][3], \
                        base + O_B + rterm + bxor); \
            } \
            _Pragma("unroll") \
            for (int np = 0; np < 4; np++) { \
                _Pragma("unroll") \
                for (int msub = 0; msub < 2; msub++) { \
                    MMA_F16(acc[msub][np * 2],     a[msub][0], a[msub][1], a[msub][2], a[msub][3], bb[np][0], bb[np][1]); \
                    MMA_F16(acc[msub][np * 2 + 1], a[msub][0], a[msub][1], a[msub][2], a[msub][3], bb[np][2], bb[np][3]); \
                } \
            } \
        } \
    } while (0)

    // ---- prologue: fill stages 0,1 ----
    LOAD_B(0, 0);
    LOAD_B(1, 1);
    LOAD_X(0);
    STORE_A(0);
    LOAD_X(1);
    CP_WAITG(1);          // B(0) complete (B(1) may still be in flight)
    __syncthreads();

    // ---- main pipeline over 4 k-chunks, 3 stages ----
    // chunk c lives in stage c % 3
    LOAD_B(2, 2);
    MMA_CHUNK(0);         // chunk 0 @ stage 0
    STORE_A(1);
    LOAD_X(2);
    CP_WAITG(1);          // B(1) complete
    __syncthreads();

    LOAD_B(3, 0);
    MMA_CHUNK(1);         // chunk 1 @ stage 1
    STORE_A(2);
    LOAD_X(3);
    CP_WAITG(1);          // B(2) complete
    __syncthreads();

    MMA_CHUNK(2);         // chunk 2 @ stage 2
    STORE_A(0);
    CP_WAITG(0);          // B(3) complete
    __syncthreads();

    MMA_CHUNK(0);         // chunk 3 @ stage 0   (bug was: stage "3")

    // ---- epilogue ----
    const int g4  = lane >> 2;
    const int tig = lane & 3;
    #pragma unroll
    for (int msub = 0; msub < 2; msub++) {
        int r0 = rowTile + wm * 32 + msub * 16 + g4;
        #pragma unroll
        for (int nsub = 0; nsub < 8; nsub++) {
            int c = colBase + wn * 64 + nsub * 8 + tig * 2;
            float* o0 = out + (size_t)r0 * LAYER + c;
            float* o1 = out + (size_t)(r0 + 8) * LAYER + c;
            *(float2*)o0 = make_float2(acc[msub][nsub][0], acc[msub][nsub][1]);
            *(float2*)o1 = make_float2(acc[msub][nsub][2], acc[msub][nsub][3]);
        }
    }
#undef LOAD_B
#undef LOAD_X
#undef STORE_A
#undef MMA_CHUNK
}

// ---------------------------------------------------------------------------
extern "C" void kernel_launch(void* const* d_in, const int* in_sizes, int n_in,
                              void* d_out, int out_size) {
    const float* x      = (const float*)d_in[0];
    const float* blocks = (const float*)d_in[1];
    float* out = (float*)d_out;

    cudaFuncSetAttribute(bd_mma_kernel,
                         cudaFuncAttributeMaxDynamicSharedMemorySize, SMEM_TOTAL);

    prep_b_kernel<<<128, 256>>>(blocks);
    bd_mma_kernel<<<64 * NBLK, 512, SMEM_TOTAL>>>(x, out);
}